// round 2
// baseline (speedup 1.0000x reference)
#include <cuda_runtime.h>
#include <math.h>

#define N_NODES 100000
#define IN_F 256
#define HID 128
#define OUT_F 64

// Scratch (device globals — no allocation allowed in kernel_launch).
// Two buffers, aliased across phases:
//   g_msg: gemm1 output (scaled h), later gemm2 output (scaled [mu|ls])
//   g_acc: agg1 result, re-zeroed, then agg2 result
__device__ float g_msg[(size_t)N_NODES * HID];
__device__ float g_acc[(size_t)N_NODES * HID];
__device__ int   g_deg [N_NODES];
__device__ float g_norm[N_NODES];

// ---------------------------------------------------------------------------
__global__ void zero_acc_deg_kernel() {
    const size_t n4 = (size_t)N_NODES * HID / 4;
    size_t i = (size_t)blockIdx.x * blockDim.x + threadIdx.x;
    const size_t stride = (size_t)gridDim.x * blockDim.x;
    float4 z = make_float4(0.f, 0.f, 0.f, 0.f);
    for (size_t k = i; k < n4; k += stride) ((float4*)g_acc)[k] = z;
    for (size_t k = i; k < N_NODES; k += stride) g_deg[k] = 0;
}

__global__ void zero_acc_kernel() {
    const size_t n4 = (size_t)N_NODES * HID / 4;
    size_t i = (size_t)blockIdx.x * blockDim.x + threadIdx.x;
    const size_t stride = (size_t)gridDim.x * blockDim.x;
    float4 z = make_float4(0.f, 0.f, 0.f, 0.f);
    for (size_t k = i; k < n4; k += stride) ((float4*)g_acc)[k] = z;
}

__global__ void deg_kernel(const int* __restrict__ src, int E) {
    int i = blockIdx.x * blockDim.x + threadIdx.x;
    if (i < E) atomicAdd(&g_deg[src[i]], 1);
}

__global__ void norm_kernel() {
    int i = blockIdx.x * blockDim.x + threadIdx.x;
    if (i < N_NODES) g_norm[i] = 1.0f / fmaxf((float)g_deg[i], 1.0f);
}

// ---------------------------------------------------------------------------
// GEMM1: g_msg[r, :] = (feat[r, :] @ W_shared) * g_norm[r]
// 128x128 tile, 256 threads, 8x8 microtile per thread, K-chunks of 16.
__global__ __launch_bounds__(256, 2)
void gemm1_kernel(const float* __restrict__ A, const float* __restrict__ W) {
    __shared__ float As[16][132];   // k-major, padded
    __shared__ float Bs[16][128];
    const int tid = threadIdx.x;
    const int tx = tid & 15, ty = tid >> 4;
    const int row0 = blockIdx.x * 128;

    float acc[8][8];
#pragma unroll
    for (int i = 0; i < 8; i++)
#pragma unroll
        for (int j = 0; j < 8; j++) acc[i][j] = 0.f;

    for (int k0 = 0; k0 < IN_F; k0 += 16) {
#pragma unroll
        for (int i = 0; i < 2; i++) {          // A tile: 512 float4
            int p = tid + i * 256;
            int r = p >> 2;
            int kk = (p & 3) << 2;
            int grow = row0 + r;
            float4 v = make_float4(0.f, 0.f, 0.f, 0.f);
            if (grow < N_NODES)
                v = *(const float4*)(A + (size_t)grow * IN_F + k0 + kk);
            As[kk + 0][r] = v.x; As[kk + 1][r] = v.y;
            As[kk + 2][r] = v.z; As[kk + 3][r] = v.w;
        }
#pragma unroll
        for (int i = 0; i < 2; i++) {          // B tile: 16 x 128
            int p = tid + i * 256;
            int kr = p >> 5;
            int c = (p & 31) << 2;
            *(float4*)&Bs[kr][c] = *(const float4*)(W + (size_t)(k0 + kr) * HID + c);
        }
        __syncthreads();
#pragma unroll
        for (int kk = 0; kk < 16; kk++) {
            float a[8], b[8];
            *(float4*)&a[0] = *(const float4*)&As[kk][ty * 4];
            *(float4*)&a[4] = *(const float4*)&As[kk][ty * 4 + 64];
            *(float4*)&b[0] = *(const float4*)&Bs[kk][tx * 4];
            *(float4*)&b[4] = *(const float4*)&Bs[kk][tx * 4 + 64];
#pragma unroll
            for (int i = 0; i < 8; i++)
#pragma unroll
                for (int j = 0; j < 8; j++) acc[i][j] += a[i] * b[j];
        }
        __syncthreads();
    }
#pragma unroll
    for (int i = 0; i < 8; i++) {
        int grow = row0 + ((i < 4) ? (ty * 4 + i) : (64 + ty * 4 + i - 4));
        if (grow >= N_NODES) continue;
        float nv = g_norm[grow];
        float4 v0 = make_float4(acc[i][0] * nv, acc[i][1] * nv, acc[i][2] * nv, acc[i][3] * nv);
        float4 v1 = make_float4(acc[i][4] * nv, acc[i][5] * nv, acc[i][6] * nv, acc[i][7] * nv);
        *(float4*)(g_msg + (size_t)grow * HID + tx * 4)      = v0;
        *(float4*)(g_msg + (size_t)grow * HID + tx * 4 + 64) = v1;
    }
}

// ---------------------------------------------------------------------------
// GEMM2 (fused two heads): A = relu(g_acc + b_shared), B = [W_mu | W_ls]
// g_msg[r, 0:64] = (h @ W_mu) * norm[r];  g_msg[r, 64:128] = (h @ W_ls) * norm[r]
__global__ __launch_bounds__(256, 2)
void gemm2_kernel(const float* __restrict__ Wmu, const float* __restrict__ Wls,
                  const float* __restrict__ bsh) {
    __shared__ float As[16][132];
    __shared__ float Bs[16][128];
    const int tid = threadIdx.x;
    const int tx = tid & 15, ty = tid >> 4;
    const int row0 = blockIdx.x * 128;

    float acc[8][8];
#pragma unroll
    for (int i = 0; i < 8; i++)
#pragma unroll
        for (int j = 0; j < 8; j++) acc[i][j] = 0.f;

    for (int k0 = 0; k0 < HID; k0 += 16) {
#pragma unroll
        for (int i = 0; i < 2; i++) {          // A tile from g_acc + bias + relu
            int p = tid + i * 256;
            int r = p >> 2;
            int kk = (p & 3) << 2;
            int grow = row0 + r;
            float4 v = make_float4(0.f, 0.f, 0.f, 0.f);
            if (grow < N_NODES) {
                v = *(const float4*)(g_acc + (size_t)grow * HID + k0 + kk);
                float4 bb = *(const float4*)(bsh + k0 + kk);
                v.x = fmaxf(v.x + bb.x, 0.f);
                v.y = fmaxf(v.y + bb.y, 0.f);
                v.z = fmaxf(v.z + bb.z, 0.f);
                v.w = fmaxf(v.w + bb.w, 0.f);
            }
            As[kk + 0][r] = v.x; As[kk + 1][r] = v.y;
            As[kk + 2][r] = v.z; As[kk + 3][r] = v.w;
        }
#pragma unroll
        for (int i = 0; i < 2; i++) {          // B tile: cols 0:64 = W_mu, 64:128 = W_ls
            int p = tid + i * 256;
            int kr = p >> 5;
            int c = (p & 31) << 2;
            const float* srcw = (c < 64)
                ? (Wmu + (size_t)(k0 + kr) * OUT_F + c)
                : (Wls + (size_t)(k0 + kr) * OUT_F + (c - 64));
            *(float4*)&Bs[kr][c] = *(const float4*)srcw;
        }
        __syncthreads();
#pragma unroll
        for (int kk = 0; kk < 16; kk++) {
            float a[8], b[8];
            *(float4*)&a[0] = *(const float4*)&As[kk][ty * 4];
            *(float4*)&a[4] = *(const float4*)&As[kk][ty * 4 + 64];
            *(float4*)&b[0] = *(const float4*)&Bs[kk][tx * 4];
            *(float4*)&b[4] = *(const float4*)&Bs[kk][tx * 4 + 64];
#pragma unroll
            for (int i = 0; i < 8; i++)
#pragma unroll
                for (int j = 0; j < 8; j++) acc[i][j] += a[i] * b[j];
        }
        __syncthreads();
    }
#pragma unroll
    for (int i = 0; i < 8; i++) {
        int grow = row0 + ((i < 4) ? (ty * 4 + i) : (64 + ty * 4 + i - 4));
        if (grow >= N_NODES) continue;
        float nv = g_norm[grow];
        float4 v0 = make_float4(acc[i][0] * nv, acc[i][1] * nv, acc[i][2] * nv, acc[i][3] * nv);
        float4 v1 = make_float4(acc[i][4] * nv, acc[i][5] * nv, acc[i][6] * nv, acc[i][7] * nv);
        *(float4*)(g_msg + (size_t)grow * HID + tx * 4)      = v0;
        *(float4*)(g_msg + (size_t)grow * HID + tx * 4 + 64) = v1;
    }
}

// ---------------------------------------------------------------------------
__device__ __forceinline__ void red_add_v4(float* p, float4 v) {
    asm volatile("red.global.add.v4.f32 [%0], {%1,%2,%3,%4};"
                 :: "l"(p), "f"(v.x), "f"(v.y), "f"(v.z), "f"(v.w)
                 : "memory");
}

// One warp per edge: 128 floats = 32 lanes x float4. msg/acc arrays L2-resident.
__global__ void agg_kernel(const int* __restrict__ src, const int* __restrict__ dst, int E) {
    int e = (int)(((size_t)blockIdx.x * blockDim.x + threadIdx.x) >> 5);
    int lane = threadIdx.x & 31;
    if (e >= E) return;
    int s = __ldg(src + e);
    int d = __ldg(dst + e);
    float4 v = *(const float4*)(g_msg + (size_t)s * HID + lane * 4);
    red_add_v4(g_acc + (size_t)d * HID + lane * 4, v);
}

// ---------------------------------------------------------------------------
// out[n, j] = (acc[n, j] + b_mu[j]) + noise[n, j] * exp(acc[n, 64+j] + b_ls[j])
__global__ void final_kernel(const float* __restrict__ noise,
                             const float* __restrict__ bmu,
                             const float* __restrict__ bls,
                             float* __restrict__ out) {
    int idx = blockIdx.x * blockDim.x + threadIdx.x;   // over N_NODES*16 float4 groups
    if (idx >= N_NODES * (OUT_F / 4)) return;
    int node = idx >> 4;
    int j = (idx & 15) << 2;
    float4 mu = *(const float4*)(g_acc + (size_t)node * HID + j);
    float4 ls = *(const float4*)(g_acc + (size_t)node * HID + 64 + j);
    float4 bm = *(const float4*)(bmu + j);
    float4 bl = *(const float4*)(bls + j);
    float4 nz = *(const float4*)(noise + (size_t)node * OUT_F + j);
    float4 o;
    o.x = mu.x + bm.x + nz.x * expf(ls.x + bl.x);
    o.y = mu.y + bm.y + nz.y * expf(ls.y + bl.y);
    o.z = mu.z + bm.z + nz.z * expf(ls.z + bl.z);
    o.w = mu.w + bm.w + nz.w * expf(ls.w + bl.w);
    *(float4*)(out + (size_t)node * OUT_F + j) = o;
}

// ---------------------------------------------------------------------------
extern "C" void kernel_launch(void* const* d_in, const int* in_sizes, int n_in,
                              void* d_out, int out_size) {
    const float* feat  = (const float*)d_in[0];
    const float* Wsh   = (const float*)d_in[1];
    const float* bsh   = (const float*)d_in[2];
    const float* Wmu   = (const float*)d_in[3];
    const float* bmu   = (const float*)d_in[4];
    const float* Wls   = (const float*)d_in[5];
    const float* bls   = (const float*)d_in[6];
    const float* noise = (const float*)d_in[7];
    const int*   src   = (const int*)d_in[8];
    const int*   dst   = (const int*)d_in[9];
    const int E = in_sizes[8];
    float* out = (float*)d_out;

    // 8 warps/block, 1 edge per warp -> exactly E warps
    const int agg_blocks = (E + 7) / 8;

    zero_acc_deg_kernel<<<1184, 256>>>();
    deg_kernel<<<(E + 255) / 256, 256>>>(src, E);
    norm_kernel<<<(N_NODES + 255) / 256, 256>>>();
    gemm1_kernel<<<(N_NODES + 127) / 128, 256>>>(feat, Wsh);
    agg_kernel<<<agg_blocks, 256>>>(src, dst, E);     // layer 1: g_msg -> g_acc
    gemm2_kernel<<<(N_NODES + 127) / 128, 256>>>(Wmu, Wls, bsh);
    zero_acc_kernel<<<1184, 256>>>();
    agg_kernel<<<agg_blocks, 256>>>(src, dst, E);     // layer 2: g_msg -> g_acc
    final_kernel<<<(N_NODES * (OUT_F / 4) + 255) / 256, 256>>>(noise, bmu, bls, out);
}

// round 3
// speedup vs baseline: 1.7431x; 1.7431x over previous
#include <cuda_runtime.h>
#include <math.h>

#define N_NODES 100000
#define IN_F 256
#define HID 128
#define OUT_F 64
#define E_MAX 1600000
#define SCAN_B 1024
#define SCAN_NB ((N_NODES + SCAN_B - 1) / SCAN_B)   // 98

// Scratch (device globals — no allocation allowed in kernel_launch).
__device__ float g_msg[(size_t)N_NODES * HID];   // gemm1 out, then gemm2 out
__device__ float g_acc[(size_t)N_NODES * HID];   // relu(h) after agg1
__device__ int   g_deg_src[N_NODES];
__device__ int   g_deg_dst[N_NODES];
__device__ float g_norm[N_NODES];
__device__ int   g_off[N_NODES + 1];
__device__ int   g_cursor[N_NODES];
__device__ int   g_csr[E_MAX];
__device__ int   g_bsum[SCAN_NB];
__device__ int   g_boff[SCAN_NB];

// ---------------------------------------------------------------------------
__global__ void zero_deg_kernel() {
    int i = blockIdx.x * blockDim.x + threadIdx.x;
    if (i < N_NODES) { g_deg_src[i] = 0; g_deg_dst[i] = 0; }
}

__global__ void hist_kernel(const int* __restrict__ src, const int* __restrict__ dst, int E) {
    int i = blockIdx.x * blockDim.x + threadIdx.x;
    if (i < E) {
        atomicAdd(&g_deg_src[src[i]], 1);
        atomicAdd(&g_deg_dst[dst[i]], 1);
    }
}

// Per-block inclusive scan of deg_dst (Hillis-Steele), write block-exclusive part.
__global__ void scan1_kernel() {
    __shared__ int sh[SCAN_B];
    int tid = threadIdx.x;
    int i = blockIdx.x * SCAN_B + tid;
    int v = (i < N_NODES) ? g_deg_dst[i] : 0;
    sh[tid] = v;
    __syncthreads();
    for (int off = 1; off < SCAN_B; off <<= 1) {
        int t = (tid >= off) ? sh[tid - off] : 0;
        __syncthreads();
        sh[tid] += t;
        __syncthreads();
    }
    if (i < N_NODES) g_off[i] = sh[tid] - v;        // exclusive within block
    if (tid == SCAN_B - 1) g_bsum[blockIdx.x] = sh[tid];
}

// Scan the 98 block sums (single block).
__global__ void scan2_kernel() {
    __shared__ int sh[128];
    int tid = threadIdx.x;
    int v = (tid < SCAN_NB) ? g_bsum[tid] : 0;
    sh[tid] = v;
    __syncthreads();
    for (int off = 1; off < 128; off <<= 1) {
        int t = (tid >= off) ? sh[tid - off] : 0;
        __syncthreads();
        sh[tid] += t;
        __syncthreads();
    }
    if (tid < SCAN_NB) g_boff[tid] = sh[tid] - v;
}

// Finalize offsets, init cursors, compute norm = 1/max(out_deg,1).
__global__ void scan3_kernel(int E) {
    int i = blockIdx.x * blockDim.x + threadIdx.x;
    if (i < N_NODES) {
        int off = g_off[i] + g_boff[i / SCAN_B];
        g_off[i] = off;
        g_cursor[i] = off;
        g_norm[i] = 1.0f / fmaxf((float)g_deg_src[i], 1.0f);
    }
    if (i == 0) g_off[N_NODES] = E;
}

__global__ void scatter_kernel(const int* __restrict__ src, const int* __restrict__ dst, int E) {
    int i = blockIdx.x * blockDim.x + threadIdx.x;
    if (i < E) {
        int pos = atomicAdd(&g_cursor[dst[i]], 1);
        g_csr[pos] = src[i];
    }
}

// ---------------------------------------------------------------------------
// GEMM1: g_msg[r, :] = (feat[r, :] @ W_shared) * g_norm[r]
__global__ __launch_bounds__(256, 2)
void gemm1_kernel(const float* __restrict__ A, const float* __restrict__ W) {
    __shared__ float As[16][132];
    __shared__ float Bs[16][128];
    const int tid = threadIdx.x;
    const int tx = tid & 15, ty = tid >> 4;
    const int row0 = blockIdx.x * 128;

    float acc[8][8];
#pragma unroll
    for (int i = 0; i < 8; i++)
#pragma unroll
        for (int j = 0; j < 8; j++) acc[i][j] = 0.f;

    for (int k0 = 0; k0 < IN_F; k0 += 16) {
#pragma unroll
        for (int i = 0; i < 2; i++) {
            int p = tid + i * 256;
            int r = p >> 2;
            int kk = (p & 3) << 2;
            int grow = row0 + r;
            float4 v = make_float4(0.f, 0.f, 0.f, 0.f);
            if (grow < N_NODES)
                v = *(const float4*)(A + (size_t)grow * IN_F + k0 + kk);
            As[kk + 0][r] = v.x; As[kk + 1][r] = v.y;
            As[kk + 2][r] = v.z; As[kk + 3][r] = v.w;
        }
#pragma unroll
        for (int i = 0; i < 2; i++) {
            int p = tid + i * 256;
            int kr = p >> 5;
            int c = (p & 31) << 2;
            *(float4*)&Bs[kr][c] = *(const float4*)(W + (size_t)(k0 + kr) * HID + c);
        }
        __syncthreads();
#pragma unroll
        for (int kk = 0; kk < 16; kk++) {
            float a[8], b[8];
            *(float4*)&a[0] = *(const float4*)&As[kk][ty * 4];
            *(float4*)&a[4] = *(const float4*)&As[kk][ty * 4 + 64];
            *(float4*)&b[0] = *(const float4*)&Bs[kk][tx * 4];
            *(float4*)&b[4] = *(const float4*)&Bs[kk][tx * 4 + 64];
#pragma unroll
            for (int i = 0; i < 8; i++)
#pragma unroll
                for (int j = 0; j < 8; j++) acc[i][j] += a[i] * b[j];
        }
        __syncthreads();
    }
#pragma unroll
    for (int i = 0; i < 8; i++) {
        int grow = row0 + ((i < 4) ? (ty * 4 + i) : (64 + ty * 4 + i - 4));
        if (grow >= N_NODES) continue;
        float nv = g_norm[grow];
        float4 v0 = make_float4(acc[i][0] * nv, acc[i][1] * nv, acc[i][2] * nv, acc[i][3] * nv);
        float4 v1 = make_float4(acc[i][4] * nv, acc[i][5] * nv, acc[i][6] * nv, acc[i][7] * nv);
        *(float4*)(g_msg + (size_t)grow * HID + tx * 4)      = v0;
        *(float4*)(g_msg + (size_t)grow * HID + tx * 4 + 64) = v1;
    }
}

// ---------------------------------------------------------------------------
// GEMM2 (fused heads): A = g_acc (already relu(h)+bias), B = [W_mu | W_ls]
__global__ __launch_bounds__(256, 2)
void gemm2_kernel(const float* __restrict__ Wmu, const float* __restrict__ Wls) {
    __shared__ float As[16][132];
    __shared__ float Bs[16][128];
    const int tid = threadIdx.x;
    const int tx = tid & 15, ty = tid >> 4;
    const int row0 = blockIdx.x * 128;

    float acc[8][8];
#pragma unroll
    for (int i = 0; i < 8; i++)
#pragma unroll
        for (int j = 0; j < 8; j++) acc[i][j] = 0.f;

    for (int k0 = 0; k0 < HID; k0 += 16) {
#pragma unroll
        for (int i = 0; i < 2; i++) {
            int p = tid + i * 256;
            int r = p >> 2;
            int kk = (p & 3) << 2;
            int grow = row0 + r;
            float4 v = make_float4(0.f, 0.f, 0.f, 0.f);
            if (grow < N_NODES)
                v = *(const float4*)(g_acc + (size_t)grow * HID + k0 + kk);
            As[kk + 0][r] = v.x; As[kk + 1][r] = v.y;
            As[kk + 2][r] = v.z; As[kk + 3][r] = v.w;
        }
#pragma unroll
        for (int i = 0; i < 2; i++) {
            int p = tid + i * 256;
            int kr = p >> 5;
            int c = (p & 31) << 2;
            const float* srcw = (c < 64)
                ? (Wmu + (size_t)(k0 + kr) * OUT_F + c)
                : (Wls + (size_t)(k0 + kr) * OUT_F + (c - 64));
            *(float4*)&Bs[kr][c] = *(const float4*)srcw;
        }
        __syncthreads();
#pragma unroll
        for (int kk = 0; kk < 16; kk++) {
            float a[8], b[8];
            *(float4*)&a[0] = *(const float4*)&As[kk][ty * 4];
            *(float4*)&a[4] = *(const float4*)&As[kk][ty * 4 + 64];
            *(float4*)&b[0] = *(const float4*)&Bs[kk][tx * 4];
            *(float4*)&b[4] = *(const float4*)&Bs[kk][tx * 4 + 64];
#pragma unroll
            for (int i = 0; i < 8; i++)
#pragma unroll
                for (int j = 0; j < 8; j++) acc[i][j] += a[i] * b[j];
        }
        __syncthreads();
    }
#pragma unroll
    for (int i = 0; i < 8; i++) {
        int grow = row0 + ((i < 4) ? (ty * 4 + i) : (64 + ty * 4 + i - 4));
        if (grow >= N_NODES) continue;
        float nv = g_norm[grow];
        float4 v0 = make_float4(acc[i][0] * nv, acc[i][1] * nv, acc[i][2] * nv, acc[i][3] * nv);
        float4 v1 = make_float4(acc[i][4] * nv, acc[i][5] * nv, acc[i][6] * nv, acc[i][7] * nv);
        *(float4*)(g_msg + (size_t)grow * HID + tx * 4)      = v0;
        *(float4*)(g_msg + (size_t)grow * HID + tx * 4 + 64) = v1;
    }
}

// ---------------------------------------------------------------------------
// CSR aggregation, one warp per destination node; lane owns cols [4L, 4L+4).
__device__ __forceinline__ float4 warp_gather_sum(int n, int lane) {
    int beg = g_off[n];
    int end = g_off[n + 1];
    float4 acc = make_float4(0.f, 0.f, 0.f, 0.f);
    for (int base = beg; base < end; base += 32) {
        int idx = base + lane;
        int eid = (idx < end) ? g_csr[idx] : 0;
        int cnt = min(32, end - base);
        for (int k = 0; k < cnt; k++) {
            int s = __shfl_sync(0xffffffffu, eid, k);
            float4 v = *(const float4*)(g_msg + (size_t)s * HID + lane * 4);
            acc.x += v.x; acc.y += v.y; acc.z += v.z; acc.w += v.w;
        }
    }
    return acc;
}

// agg pass 1: g_acc[n,:] = relu(sum + b_shared)
__global__ void agg1_kernel(const float* __restrict__ bsh) {
    int n = (int)(((size_t)blockIdx.x * blockDim.x + threadIdx.x) >> 5);
    int lane = threadIdx.x & 31;
    if (n >= N_NODES) return;
    float4 acc = warp_gather_sum(n, lane);
    float4 bb = *(const float4*)(bsh + lane * 4);
    float4 o;
    o.x = fmaxf(acc.x + bb.x, 0.f);
    o.y = fmaxf(acc.y + bb.y, 0.f);
    o.z = fmaxf(acc.z + bb.z, 0.f);
    o.w = fmaxf(acc.w + bb.w, 0.f);
    *(float4*)(g_acc + (size_t)n * HID + lane * 4) = o;
}

// agg pass 2 + reparameterize: lanes 0-15 hold mu cols, 16-31 hold ls cols.
__global__ void agg2_final_kernel(const float* __restrict__ noise,
                                  const float* __restrict__ bmu,
                                  const float* __restrict__ bls,
                                  float* __restrict__ out) {
    int n = (int)(((size_t)blockIdx.x * blockDim.x + threadIdx.x) >> 5);
    int lane = threadIdx.x & 31;
    if (n >= N_NODES) return;
    float4 acc = warp_gather_sum(n, lane);
    // exchange halves: lane L <-> lane L^16
    float4 other;
    other.x = __shfl_xor_sync(0xffffffffu, acc.x, 16);
    other.y = __shfl_xor_sync(0xffffffffu, acc.y, 16);
    other.z = __shfl_xor_sync(0xffffffffu, acc.z, 16);
    other.w = __shfl_xor_sync(0xffffffffu, acc.w, 16);
    if (lane < 16) {
        int j = lane * 4;                       // output col group
        float4 bm = *(const float4*)(bmu + j);
        float4 bl = *(const float4*)(bls + j);
        float4 nz = *(const float4*)(noise + (size_t)n * OUT_F + j);
        float4 o;
        o.x = acc.x + bm.x + nz.x * expf(other.x + bl.x);
        o.y = acc.y + bm.y + nz.y * expf(other.y + bl.y);
        o.z = acc.z + bm.z + nz.z * expf(other.z + bl.z);
        o.w = acc.w + bm.w + nz.w * expf(other.w + bl.w);
        *(float4*)(out + (size_t)n * OUT_F + j) = o;
    }
}

// ---------------------------------------------------------------------------
extern "C" void kernel_launch(void* const* d_in, const int* in_sizes, int n_in,
                              void* d_out, int out_size) {
    const float* feat  = (const float*)d_in[0];
    const float* Wsh   = (const float*)d_in[1];
    const float* bsh   = (const float*)d_in[2];
    const float* Wmu   = (const float*)d_in[3];
    const float* bmu   = (const float*)d_in[4];
    const float* Wls   = (const float*)d_in[5];
    const float* bls   = (const float*)d_in[6];
    const float* noise = (const float*)d_in[7];
    const int*   src   = (const int*)d_in[8];
    const int*   dst   = (const int*)d_in[9];
    const int E = in_sizes[8];
    float* out = (float*)d_out;

    const int agg_blocks = (N_NODES * 32 + 255) / 256;   // warp per node

    zero_deg_kernel<<<(N_NODES + 255) / 256, 256>>>();
    hist_kernel<<<(E + 255) / 256, 256>>>(src, dst, E);
    scan1_kernel<<<SCAN_NB, SCAN_B>>>();
    scan2_kernel<<<1, 128>>>();
    scan3_kernel<<<(N_NODES + 255) / 256, 256>>>(E);
    scatter_kernel<<<(E + 255) / 256, 256>>>(src, dst, E);
    gemm1_kernel<<<(N_NODES + 127) / 128, 256>>>(feat, Wsh);
    agg1_kernel<<<agg_blocks, 256>>>(bsh);
    gemm2_kernel<<<(N_NODES + 127) / 128, 256>>>(Wmu, Wls);
    agg2_final_kernel<<<agg_blocks, 256>>>(noise, bmu, bls, out);
}